// round 1
// baseline (speedup 1.0000x reference)
#include <cuda_runtime.h>
#include <cuda_bf16.h>
#include <cstdint>

#define NROWS 65536
#define D 128

// ---------------- scratch (__device__ globals; allocation-free) ----------------
__device__ float g_TE[(size_t)2 * NROWS * D];          // 64 MB  time encodings, both branches
__device__ float g_G [(size_t)2 * NROWS * 768];        // 402 MB gi(384) | gh(384), both branches
__device__ int   g_hidx[NROWS];                        // n_id[row]
__device__ int   g_gidx[2 * NROWS];                    // picked other index
__device__ int   g_fidx[2 * NROWS];                    // feature row index
__device__ int   g_fsrc[2 * NROWS];                    // 0=raw_msg_s, 1=raw_msg_d, 2=pos_emb

// ---------------- helpers ----------------
__device__ __forceinline__ uint32_t f2tf32(float f) {
    uint32_t u; asm("cvt.rna.tf32.f32 %0, %1;" : "=r"(u) : "f"(f)); return u;
}
__device__ __forceinline__ void st_tf4(uint32_t* p, float4 v) {
    uint4 u = make_uint4(f2tf32(v.x), f2tf32(v.y), f2tf32(v.z), f2tf32(v.w));
    *(uint4*)p = u;
}
__device__ __forceinline__ void mma_tf32(float* c, const uint32_t* a, uint32_t b0, uint32_t b1) {
    asm volatile(
        "mma.sync.aligned.m16n8k8.row.col.f32.tf32.tf32.f32 "
        "{%0,%1,%2,%3}, {%4,%5,%6,%7}, {%8,%9}, {%0,%1,%2,%3};\n"
        : "+f"(c[0]), "+f"(c[1]), "+f"(c[2]), "+f"(c[3])
        : "r"(a[0]), "r"(a[1]), "r"(a[2]), "r"(a[3]), "r"(b0), "r"(b1));
}

// ---------------- kernel 1: descriptors + time encodings + last_up ----------------
__global__ void prep_kernel(const int* __restrict__ n_id,
                            const int* __restrict__ other_s, const int* __restrict__ other_d,
                            const int* __restrict__ t_s, const int* __restrict__ t_d,
                            const int* __restrict__ last_update,
                            const float* __restrict__ w_tm, const float* __restrict__ b_tm,
                            const float* __restrict__ w_tp, const float* __restrict__ b_tp,
                            float* __restrict__ out)
{
    int row = blockIdx.x;
    int k   = threadIdx.x;                 // 0..127
    int ts = t_s[row], td = t_d[row];
    bool pick = (ts >= td);
    int nid = n_id[row];
    int tpick = pick ? ts : td;
    float trel = (float)(tpick - last_update[nid]);

    g_TE[(size_t)row * D + k]                      = cosf(trel * w_tm[k] + b_tm[k]);
    g_TE[(size_t)NROWS * D + (size_t)row * D + k]  = cosf(trel * w_tp[k] + b_tp[k]);

    if (k == 0) {
        int og = pick ? other_s[row] : other_d[row];
        g_hidx[row]          = nid;
        g_gidx[row]          = og;
        g_gidx[NROWS + row]  = og;
        g_fsrc[row]          = pick ? 0 : 1;     // raw_msg_s / raw_msg_d
        g_fidx[row]          = row;
        g_fsrc[NROWS + row]  = 2;                // pos_emb
        g_fidx[NROWS + row]  = pick ? nid : other_d[row];
        out[(size_t)2 * NROWS * D + row] = (float)tpick;   // last_up = max(t_s,t_d)
    }
}

// A-tile row pointer resolution: chunk 0 = h, 1 = gathered mem, 2 = picked feature, 3 = TE
__device__ __forceinline__ const float* resolveA(int c, int br, int R,
        const float* mem, const float* msg_s, const float* msg_d, const float* pos_emb)
{
    if (c == 0) return mem + (size_t)g_hidx[R] * D;
    if (c == 1) return mem + (size_t)g_gidx[br * NROWS + R] * D;
    if (c == 2) {
        int s = g_fsrc[br * NROWS + R];
        const float* b = (s == 0) ? msg_s : ((s == 1) ? msg_d : pos_emb);
        return b + (size_t)g_fidx[br * NROWS + R] * D;
    }
    return g_TE + ((size_t)br * NROWS + R) * D;
}

// ---------------- kernel 2: fused-gather TF32 GEMM -> G = [gi | gh] ----------------
// grid: (512 row-blocks, 6 n-blocks, 2 branches); block 256 threads; BM=128, BN=128, BK=16
__global__ void __launch_bounds__(256, 2)
gemm_kernel(const float* __restrict__ memory, const float* __restrict__ pos_mem,
            const float* __restrict__ msg_s,  const float* __restrict__ msg_d,
            const float* __restrict__ pos_emb,
            const float* __restrict__ Wih0, const float* __restrict__ Whh0,
            const float* __restrict__ Wih1, const float* __restrict__ Whh1)
{
    __shared__ uint32_t As[128][20];   // padded stride 20 -> conflict-free frag loads
    __shared__ uint32_t Ws[128][20];

    int br = blockIdx.z;
    int nb = blockIdx.y;
    int rb = blockIdx.x;
    bool is_gh = (nb >= 3);
    const float* W = is_gh ? (br ? Whh1 : Whh0) : (br ? Wih1 : Wih0);
    int Wld     = is_gh ? 128 : 512;
    int n0      = (nb - (is_gh ? 3 : 0)) * 128;
    int outc0   = is_gh ? 384 + n0 : n0;
    int nchunks = is_gh ? 1 : 4;
    const float* mem = br ? pos_mem : memory;

    int tid  = threadIdx.x;
    int lane = tid & 31, warp = tid >> 5;
    int wm = warp & 1;        // 0..1 : 64 rows
    int wn = warp >> 1;       // 0..3 : 32 cols

    float acc[4][4][4];
    #pragma unroll
    for (int i = 0; i < 4; ++i)
        #pragma unroll
        for (int j = 0; j < 4; ++j)
            #pragma unroll
            for (int q = 0; q < 4; ++q) acc[i][j][q] = 0.f;

    int lr = tid >> 2;        // loader row 0..63
    int lq = tid & 3;         // float4 quad within 16-wide k slab
    int R0 = rb * 128 + lr, R1 = R0 + 64;
    const float* wp0 = W + (size_t)(n0 + lr)      * Wld;
    const float* wp1 = W + (size_t)(n0 + lr + 64) * Wld;

    for (int c = 0; c < nchunks; ++c) {
        const float* pa0 = resolveA(c, br, R0, mem, msg_s, msg_d, pos_emb);
        const float* pa1 = resolveA(c, br, R1, mem, msg_s, msg_d, pos_emb);
        int kbase = c * 128;
        for (int kk = 0; kk < 128; kk += 16) {
            __syncthreads();
            float4 a0v = __ldg((const float4*)(pa0 + kk) + lq);
            float4 a1v = __ldg((const float4*)(pa1 + kk) + lq);
            float4 w0v = __ldg((const float4*)(wp0 + kbase + kk) + lq);
            float4 w1v = __ldg((const float4*)(wp1 + kbase + kk) + lq);
            st_tf4(&As[lr][lq * 4], a0v);
            st_tf4(&As[lr + 64][lq * 4], a1v);
            st_tf4(&Ws[lr][lq * 4], w0v);
            st_tf4(&Ws[lr + 64][lq * 4], w1v);
            __syncthreads();

            #pragma unroll
            for (int k8 = 0; k8 < 2; ++k8) {
                int kq = k8 * 8 + (lane & 3);
                uint32_t afrag[4][4];
                #pragma unroll
                for (int mf = 0; mf < 4; ++mf) {
                    int r = wm * 64 + mf * 16 + (lane >> 2);
                    afrag[mf][0] = As[r][kq];
                    afrag[mf][1] = As[r + 8][kq];
                    afrag[mf][2] = As[r][kq + 4];
                    afrag[mf][3] = As[r + 8][kq + 4];
                }
                #pragma unroll
                for (int nf = 0; nf < 4; ++nf) {
                    int ncol = wn * 32 + nf * 8 + (lane >> 2);
                    uint32_t b0 = Ws[ncol][kq];
                    uint32_t b1 = Ws[ncol][kq + 4];
                    #pragma unroll
                    for (int mf = 0; mf < 4; ++mf)
                        mma_tf32(&acc[mf][nf][0], afrag[mf], b0, b1);
                }
            }
        }
    }

    // write accumulators to G
    size_t gbase = (size_t)br * NROWS * 768;
    #pragma unroll
    for (int mf = 0; mf < 4; ++mf) {
        int r = rb * 128 + wm * 64 + mf * 16 + (lane >> 2);
        #pragma unroll
        for (int nf = 0; nf < 4; ++nf) {
            int cgl = outc0 + wn * 32 + nf * 8 + (lane & 3) * 2;
            *(float2*)&g_G[gbase + (size_t)r * 768 + cgl]       = make_float2(acc[mf][nf][0], acc[mf][nf][1]);
            *(float2*)&g_G[gbase + (size_t)(r + 8) * 768 + cgl] = make_float2(acc[mf][nf][2], acc[mf][nf][3]);
        }
    }
}

// ---------------- kernel 3: GRU epilogue ----------------
__global__ void gru_kernel(const float* __restrict__ memory, const float* __restrict__ pos_mem,
                           const float* __restrict__ bih0, const float* __restrict__ bhh0,
                           const float* __restrict__ bih1, const float* __restrict__ bhh1,
                           float* __restrict__ out)
{
    int row = blockIdx.x;
    int j   = threadIdx.x;     // 0..127
    int hidx = g_hidx[row];
    #pragma unroll
    for (int br = 0; br < 2; ++br) {
        const float* G   = g_G + ((size_t)br * NROWS + row) * 768;
        const float* bih = br ? bih1 : bih0;
        const float* bhh = br ? bhh1 : bhh0;
        const float* mem = br ? pos_mem : memory;
        float ir  = G[j]       + bih[j];
        float iz  = G[128 + j] + bih[128 + j];
        float inn = G[256 + j] + bih[256 + j];
        float hr  = G[384 + j] + bhh[j];
        float hz  = G[512 + j] + bhh[128 + j];
        float hn  = G[640 + j] + bhh[256 + j];
        float h   = mem[(size_t)hidx * D + j];
        float r   = 1.f / (1.f + expf(-(ir + hr)));
        float z   = 1.f / (1.f + expf(-(iz + hz)));
        float nn  = tanhf(inn + r * hn);
        out[((size_t)br * NROWS + row) * D + j] = (1.f - z) * nn + z * h;
    }
}

// ---------------- launch ----------------
extern "C" void kernel_launch(void* const* d_in, const int* in_sizes, int n_in,
                              void* d_out, int out_size)
{
    const int*   n_id        = (const int*)  d_in[0];
    const float* memory      = (const float*)d_in[1];
    const float* pos_mem     = (const float*)d_in[2];
    const float* pos_emb     = (const float*)d_in[3];
    const float* raw_msg_s   = (const float*)d_in[4];
    const float* raw_msg_d   = (const float*)d_in[5];
    const int*   other_s     = (const int*)  d_in[6];
    const int*   other_d     = (const int*)  d_in[7];
    const int*   t_s         = (const int*)  d_in[8];
    const int*   t_d         = (const int*)  d_in[9];
    const int*   last_update = (const int*)  d_in[10];
    const float* w_time_mem  = (const float*)d_in[11];
    const float* b_time_mem  = (const float*)d_in[12];
    const float* w_time_pos  = (const float*)d_in[13];
    const float* b_time_pos  = (const float*)d_in[14];
    const float* Wih_mem     = (const float*)d_in[15];
    const float* Whh_mem     = (const float*)d_in[16];
    const float* bih_mem     = (const float*)d_in[17];
    const float* bhh_mem     = (const float*)d_in[18];
    const float* Wih_pos     = (const float*)d_in[19];
    const float* Whh_pos     = (const float*)d_in[20];
    const float* bih_pos     = (const float*)d_in[21];
    const float* bhh_pos     = (const float*)d_in[22];
    float* out = (float*)d_out;

    prep_kernel<<<NROWS, 128>>>(n_id, other_s, other_d, t_s, t_d, last_update,
                                w_time_mem, b_time_mem, w_time_pos, b_time_pos, out);

    gemm_kernel<<<dim3(NROWS / 128, 6, 2), 256>>>(memory, pos_mem,
                                                  raw_msg_s, raw_msg_d, pos_emb,
                                                  Wih_mem, Whh_mem, Wih_pos, Whh_pos);

    gru_kernel<<<NROWS, 128>>>(memory, pos_mem, bih_mem, bhh_mem, bih_pos, bhh_pos, out);
}

// round 2
// speedup vs baseline: 1.1321x; 1.1321x over previous
#include <cuda_runtime.h>
#include <cstdint>

#define NROWS 65536
#define D 128
#define TMAX 2048   // trel in [1, 2000)

// ---------------- scratch (__device__ globals; allocation-free) ----------------
__device__ float g_G[(size_t)2 * NROWS * 512];   // per row: [r_sum | z_sum | inn | hn]
__device__ float g_TEtab[2 * TMAX * D];          // cos tables, both branches (2 MB)
__device__ float g_Wih[2][384 * 512];            // RNA-rounded tf32 weights
__device__ float g_Whh[2][384 * 128];
__device__ int   g_hidx[NROWS];
__device__ int   g_gidx[NROWS];
__device__ int   g_trel[NROWS];
__device__ int   g_fidx1[NROWS];
__device__ int   g_pick[NROWS];

// ---------------- helpers ----------------
__device__ __forceinline__ void mma_tf32(float* c, const uint32_t* a, uint32_t b0, uint32_t b1) {
    asm volatile(
        "mma.sync.aligned.m16n8k8.row.col.f32.tf32.tf32.f32 "
        "{%0,%1,%2,%3}, {%4,%5,%6,%7}, {%8,%9}, {%0,%1,%2,%3};\n"
        : "+f"(c[0]), "+f"(c[1]), "+f"(c[2]), "+f"(c[3])
        : "r"(a[0]), "r"(a[1]), "r"(a[2]), "r"(a[3]), "r"(b0), "r"(b1));
}
__device__ __forceinline__ void cp16(uint32_t dst, const void* src) {
    asm volatile("cp.async.cg.shared.global [%0], [%1], 16;\n" :: "r"(dst), "l"(src));
}
// swizzled float index within a 128x16 tile stored as 64 macro-rows x 32 floats
__device__ __forceinline__ int SW(int r, int k) {
    int m  = r >> 1;
    int ch = ((r & 1) << 2) | (k >> 2);
    return m * 32 + (((ch ^ (m & 7))) << 2) + (k & 3);
}

// ---------------- kernel: cos lookup tables ----------------
__global__ void te_table_kernel(const float* __restrict__ wm, const float* __restrict__ bm,
                                const float* __restrict__ wp, const float* __restrict__ bp)
{
    int t = blockIdx.x, k = threadIdx.x;
    float tf = (float)t;
    g_TEtab[t * D + k]            = cosf(tf * wm[k] + bm[k]);
    g_TEtab[TMAX * D + t * D + k] = cosf(tf * wp[k] + bp[k]);
}

// ---------------- kernel: RNA-round weights to tf32 ----------------
__global__ void wround_kernel(const float* __restrict__ Wih0, const float* __restrict__ Wih1,
                              const float* __restrict__ Whh0, const float* __restrict__ Whh1)
{
    int which = blockIdx.y;
    int n = (which < 2) ? 384 * 512 : 384 * 128;
    int i = blockIdx.x * 256 + threadIdx.x;
    if (i >= n) return;
    const float* s = (which == 0) ? Wih0 : (which == 1) ? Wih1 : (which == 2) ? Whh0 : Whh1;
    float* dvec    = (which == 0) ? g_Wih[0] : (which == 1) ? g_Wih[1] : (which == 2) ? g_Whh[0] : g_Whh[1];
    uint32_t u; asm("cvt.rna.tf32.f32 %0, %1;" : "=r"(u) : "f"(s[i]));
    dvec[i] = __uint_as_float(u);
}

// ---------------- kernel: descriptors + last_up ----------------
__global__ void prep_kernel(const int* __restrict__ n_id,
                            const int* __restrict__ other_s, const int* __restrict__ other_d,
                            const int* __restrict__ t_s, const int* __restrict__ t_d,
                            const int* __restrict__ last_update,
                            float* __restrict__ out)
{
    int row = blockIdx.x * 256 + threadIdx.x;
    if (row >= NROWS) return;
    int ts = t_s[row], td = t_d[row];
    bool pick = (ts >= td);
    int nid = n_id[row];
    int tpick = pick ? ts : td;
    g_hidx[row]  = nid;
    g_gidx[row]  = pick ? other_s[row] : other_d[row];
    g_trel[row]  = tpick - last_update[nid];
    g_pick[row]  = pick ? 1 : 0;
    g_fidx1[row] = pick ? nid : other_d[row];
    out[(size_t)2 * NROWS * D + row] = (float)tpick;   // last_up = max(t_s,t_d)
}

// ---------------- kernel: pipelined fused-gather TF32 GEMM ----------------
// grid (512 row-blocks, 4 gate-blocks, 2 branches); 256 threads; BM=128, BN=128, BK=16
// gate blocks: nb0 = r_sum (5 K-chunks), nb1 = z_sum (5), nb2 = inn (4), nb3 = hn (1)
__global__ void __launch_bounds__(256, 2)
gemm_kernel(const float* __restrict__ memory, const float* __restrict__ pos_mem,
            const float* __restrict__ msg_s,  const float* __restrict__ msg_d,
            const float* __restrict__ pos_emb)
{
    __shared__ float As[3][2048];
    __shared__ float Ws[3][2048];

    int br = blockIdx.z, nb = blockIdx.y, rb = blockIdx.x;
    int nchunks = (nb == 3) ? 1 : ((nb == 2) ? 4 : 5);
    int NS = nchunks * 8;
    const float* mem  = br ? pos_mem : memory;
    const float* WihB = g_Wih[br];
    const float* WhhB = g_Whh[br];
    const float* TEb  = g_TEtab + br * TMAX * D;

    int tid = threadIdx.x, lane = tid & 31, warp = tid >> 5;
    int wm = warp & 1, wn = warp >> 1;

    // loader assignment: rows lr0 and lr0+64, 16B k-chunk koff
    int lr0 = tid >> 2;
    int R0 = rb * 128 + lr0, R1 = R0 + 64;
    int koff = (tid & 3) * 4;

    const float *ha0, *ha1, *ga0, *ga1, *fa0, *fa1, *ta0, *ta1;
    {
        ha0 = mem + (size_t)g_hidx[R0] * D;  ha1 = mem + (size_t)g_hidx[R1] * D;
        ga0 = mem + (size_t)g_gidx[R0] * D;  ga1 = mem + (size_t)g_gidx[R1] * D;
        ta0 = TEb + g_trel[R0] * D;          ta1 = TEb + g_trel[R1] * D;
        if (br == 0) {
            fa0 = (g_pick[R0] ? msg_s : msg_d) + (size_t)R0 * D;
            fa1 = (g_pick[R1] ? msg_s : msg_d) + (size_t)R1 * D;
        } else {
            fa0 = pos_emb + (size_t)g_fidx1[R0] * D;
            fa1 = pos_emb + (size_t)g_fidx1[R1] * D;
        }
    }

    // swizzled smem destination byte offsets (same formula for A and W tiles)
    uint32_t off0 = (uint32_t)(((tid >> 3) * 32 + ((tid & 7) ^ ((tid >> 3) & 7)) * 4) * 4);
    uint32_t off1 = off0 + 1024 * 4;
    uint32_t aS[3], wS[3];
    #pragma unroll
    for (int s = 0; s < 3; ++s) {
        aS[s] = (uint32_t)__cvta_generic_to_shared(As[s]);
        wS[s] = (uint32_t)__cvta_generic_to_shared(Ws[s]);
    }

    auto issue = [&](int s) {
        if (s < NS) {
            int c = s >> 3, kk = (s & 7) * 16;
            const float *p0, *p1;
            if      (c == 1) { p0 = ga0; p1 = ga1; }
            else if (c == 2) { p0 = fa0; p1 = fa1; }
            else if (c == 3) { p0 = ta0; p1 = ta1; }
            else             { p0 = ha0; p1 = ha1; }
            int st = s % 3;
            cp16(aS[st] + off0, p0 + kk + koff);
            cp16(aS[st] + off1, p1 + kk + koff);
            const float *w0, *w1;
            if (c < 4 && nb < 3) {
                const float* wb = WihB + (size_t)(nb * 128) * 512 + c * 128;
                w0 = wb + (size_t)lr0 * 512;
                w1 = wb + (size_t)(lr0 + 64) * 512;
            } else {
                const float* wb = WhhB + (size_t)((nb < 3 ? nb : 2) * 128) * 128;
                w0 = wb + lr0 * 128;
                w1 = wb + (lr0 + 64) * 128;
            }
            cp16(wS[st] + off0, w0 + kk + koff);
            cp16(wS[st] + off1, w1 + kk + koff);
        }
        asm volatile("cp.async.commit_group;\n");
    };

    float acc[4][4][4];
    #pragma unroll
    for (int i = 0; i < 4; ++i)
        #pragma unroll
        for (int j = 0; j < 4; ++j)
            #pragma unroll
            for (int q = 0; q < 4; ++q) acc[i][j][q] = 0.f;

    issue(0);
    issue(1);

    for (int s = 0; s < NS; ++s) {
        asm volatile("cp.async.wait_group 1;\n");
        __syncthreads();
        issue(s + 2);

        const uint32_t* A = (const uint32_t*)As[s % 3];
        const uint32_t* W = (const uint32_t*)Ws[s % 3];
        #pragma unroll
        for (int k8 = 0; k8 < 2; ++k8) {
            int kq = k8 * 8 + (lane & 3);
            uint32_t af[4][4];
            #pragma unroll
            for (int mf = 0; mf < 4; ++mf) {
                int r = wm * 64 + mf * 16 + (lane >> 2);
                af[mf][0] = A[SW(r,     kq)];
                af[mf][1] = A[SW(r + 8, kq)];
                af[mf][2] = A[SW(r,     kq + 4)];
                af[mf][3] = A[SW(r + 8, kq + 4)];
            }
            #pragma unroll
            for (int nf = 0; nf < 4; ++nf) {
                int nc = wn * 32 + nf * 8 + (lane >> 2);
                uint32_t b0 = W[SW(nc, kq)];
                uint32_t b1 = W[SW(nc, kq + 4)];
                #pragma unroll
                for (int mf = 0; mf < 4; ++mf)
                    mma_tf32(&acc[mf][nf][0], af[mf], b0, b1);
            }
        }
    }

    // store to G: per row 512 cols = [r_sum | z_sum | inn | hn]
    size_t gb = (size_t)br * NROWS * 512;
    #pragma unroll
    for (int mf = 0; mf < 4; ++mf) {
        int r = rb * 128 + wm * 64 + mf * 16 + (lane >> 2);
        #pragma unroll
        for (int nf = 0; nf < 4; ++nf) {
            int col = nb * 128 + wn * 32 + nf * 8 + (lane & 3) * 2;
            *(float2*)&g_G[gb + (size_t)r * 512 + col]       = make_float2(acc[mf][nf][0], acc[mf][nf][1]);
            *(float2*)&g_G[gb + (size_t)(r + 8) * 512 + col] = make_float2(acc[mf][nf][2], acc[mf][nf][3]);
        }
    }
}

// ---------------- kernel: GRU epilogue ----------------
__global__ void gru_kernel(const float* __restrict__ memory, const float* __restrict__ pos_mem,
                           const float* __restrict__ bih0, const float* __restrict__ bhh0,
                           const float* __restrict__ bih1, const float* __restrict__ bhh1,
                           float* __restrict__ out)
{
    int row = blockIdx.x;
    int j   = threadIdx.x;
    int hidx = g_hidx[row];
    #pragma unroll
    for (int br = 0; br < 2; ++br) {
        const float* G   = g_G + ((size_t)br * NROWS + row) * 512;
        const float* bih = br ? bih1 : bih0;
        const float* bhh = br ? bhh1 : bhh0;
        const float* mem = br ? pos_mem : memory;
        float r  = 1.f / (1.f + expf(-(G[j]       + bih[j]       + bhh[j])));
        float z  = 1.f / (1.f + expf(-(G[128 + j] + bih[128 + j] + bhh[128 + j])));
        float nn = tanhf(G[256 + j] + bih[256 + j] + r * (G[384 + j] + bhh[256 + j]));
        float h  = mem[(size_t)hidx * D + j];
        out[((size_t)br * NROWS + row) * D + j] = (1.f - z) * nn + z * h;
    }
}

// ---------------- launch ----------------
extern "C" void kernel_launch(void* const* d_in, const int* in_sizes, int n_in,
                              void* d_out, int out_size)
{
    const int*   n_id        = (const int*)  d_in[0];
    const float* memory      = (const float*)d_in[1];
    const float* pos_mem     = (const float*)d_in[2];
    const float* pos_emb     = (const float*)d_in[3];
    const float* raw_msg_s   = (const float*)d_in[4];
    const float* raw_msg_d   = (const float*)d_in[5];
    const int*   other_s     = (const int*)  d_in[6];
    const int*   other_d     = (const int*)  d_in[7];
    const int*   t_s         = (const int*)  d_in[8];
    const int*   t_d         = (const int*)  d_in[9];
    const int*   last_update = (const int*)  d_in[10];
    const float* w_time_mem  = (const float*)d_in[11];
    const float* b_time_mem  = (const float*)d_in[12];
    const float* w_time_pos  = (const float*)d_in[13];
    const float* b_time_pos  = (const float*)d_in[14];
    const float* Wih_mem     = (const float*)d_in[15];
    const float* Whh_mem     = (const float*)d_in[16];
    const float* bih_mem     = (const float*)d_in[17];
    const float* bhh_mem     = (const float*)d_in[18];
    const float* Wih_pos     = (const float*)d_in[19];
    const float* Whh_pos     = (const float*)d_in[20];
    const float* bih_pos     = (const float*)d_in[21];
    const float* bhh_pos     = (const float*)d_in[22];
    float* out = (float*)d_out;

    te_table_kernel<<<TMAX, 128>>>(w_time_mem, b_time_mem, w_time_pos, b_time_pos);
    wround_kernel<<<dim3(768, 4), 256>>>(Wih_mem, Wih_pos, Whh_mem, Whh_pos);
    prep_kernel<<<NROWS / 256, 256>>>(n_id, other_s, other_d, t_s, t_d, last_update, out);

    gemm_kernel<<<dim3(NROWS / 128, 4, 2), 256>>>(memory, pos_mem,
                                                  raw_msg_s, raw_msg_d, pos_emb);

    gru_kernel<<<NROWS, 128>>>(memory, pos_mem, bih_mem, bhh_mem, bih_pos, bhh_pos, out);
}

// round 4
// speedup vs baseline: 1.3368x; 1.1808x over previous
#include <cuda_runtime.h>
#include <cstdint>

#define NROWS 65536
#define D 128
#define TMAX 2048

// smem: rp table 4KB | A stages 3*16KB | W stages 3*16KB
#define RP_BYTES 4096
#define A_OFF    4096
#define W_OFF    (4096 + 3 * 16384)
#define SMEM_SZ  (4096 + 6 * 16384)

// ---------------- scratch ----------------
__device__ float g_G[(size_t)2 * NROWS * 512];   // per row: [r_sum | z_sum | inn | hn]
__device__ float g_TEtab[2 * TMAX * D];
__device__ float g_Wih[2][384 * 512];
__device__ float g_Whh[2][384 * 128];
__device__ int g_hidx[NROWS], g_gidx[NROWS], g_trel[NROWS], g_fidx1[NROWS], g_pick[NROWS];

// ---------------- ptx helpers ----------------
__device__ __forceinline__ void mma_tf32(float* c, const uint32_t* a, uint32_t b0, uint32_t b1) {
    asm volatile(
        "mma.sync.aligned.m16n8k8.row.col.f32.tf32.tf32.f32 "
        "{%0,%1,%2,%3}, {%4,%5,%6,%7}, {%8,%9}, {%0,%1,%2,%3};\n"
        : "+f"(c[0]), "+f"(c[1]), "+f"(c[2]), "+f"(c[3])
        : "r"(a[0]), "r"(a[1]), "r"(a[2]), "r"(a[3]), "r"(b0), "r"(b1));
}
__device__ __forceinline__ void cp16(uint32_t dst, const void* src) {
    asm volatile("cp.async.cg.shared.global [%0], [%1], 16;\n" :: "r"(dst), "l"(src));
}
__device__ __forceinline__ void ldsm4(uint32_t* r, uint32_t addr) {
    asm volatile("ldmatrix.sync.aligned.m8n8.x4.shared.b16 {%0,%1,%2,%3}, [%4];"
                 : "=r"(r[0]), "=r"(r[1]), "=r"(r[2]), "=r"(r[3]) : "r"(addr));
}

// ---------------- small kernels ----------------
__global__ void te_table_kernel(const float* __restrict__ wm, const float* __restrict__ bm,
                                const float* __restrict__ wp, const float* __restrict__ bp)
{
    int t = blockIdx.x, k = threadIdx.x;
    float tf = (float)t;
    g_TEtab[t * D + k]            = cosf(tf * wm[k] + bm[k]);
    g_TEtab[TMAX * D + t * D + k] = cosf(tf * wp[k] + bp[k]);
}

__global__ void wround_kernel(const float* __restrict__ Wih0, const float* __restrict__ Wih1,
                              const float* __restrict__ Whh0, const float* __restrict__ Whh1)
{
    int which = blockIdx.y;
    int n = (which < 2) ? 384 * 512 : 384 * 128;
    int i = blockIdx.x * 256 + threadIdx.x;
    if (i >= n) return;
    const float* s = (which == 0) ? Wih0 : (which == 1) ? Wih1 : (which == 2) ? Whh0 : Whh1;
    float* dv      = (which == 0) ? g_Wih[0] : (which == 1) ? g_Wih[1] : (which == 2) ? g_Whh[0] : g_Whh[1];
    uint32_t u; asm("cvt.rna.tf32.f32 %0, %1;" : "=r"(u) : "f"(s[i]));
    dv[i] = __uint_as_float(u);
}

__global__ void prep_kernel(const int* __restrict__ n_id,
                            const int* __restrict__ other_s, const int* __restrict__ other_d,
                            const int* __restrict__ t_s, const int* __restrict__ t_d,
                            const int* __restrict__ last_update,
                            float* __restrict__ out)
{
    int row = blockIdx.x * 256 + threadIdx.x;
    if (row >= NROWS) return;
    int ts = t_s[row], td = t_d[row];
    bool pick = (ts >= td);
    int nid = n_id[row];
    int tpick = pick ? ts : td;
    g_hidx[row]  = nid;
    g_gidx[row]  = pick ? other_s[row] : other_d[row];
    g_trel[row]  = tpick - last_update[nid];
    g_pick[row]  = pick ? 1 : 0;
    g_fidx1[row] = pick ? nid : other_d[row];
    out[(size_t)2 * NROWS * D + row] = (float)tpick;
}

// ---------------- pipelined TF32 GEMM, ldmatrix fragments, BK=32 ----------------
// grid (512 row-blocks, 4 gate-blocks, 2 branches); 256 threads; BM=128, BN=128.
// gates: nb0=r_sum (20 slabs: 16 Wih + 4 Whh), nb1=z_sum (20), nb2=inn (16), nb3=hn (4)
__global__ void __launch_bounds__(256, 2)
gemm_kernel(const float* __restrict__ memory, const float* __restrict__ pos_mem,
            const float* __restrict__ msg_s,  const float* __restrict__ msg_d,
            const float* __restrict__ pos_emb)
{
    extern __shared__ char sm[];
    const char** rp = (const char**)sm;
    uint32_t su = (uint32_t)__cvta_generic_to_shared(sm);

    int br = blockIdx.z, nb = blockIdx.y, rb = blockIdx.x;
    int NSslab = (nb == 3) ? 4 : ((nb == 2) ? 16 : 20);

    const float* mem  = br ? pos_mem : memory;
    const float* WihB = g_Wih[br];
    const float* WhhB = g_Whh[br];

    int tid = threadIdx.x, lane = tid & 31, warp = tid >> 5;
    int wm = warp & 1, wn = warp >> 1;

    if (tid < 128) {
        int R = rb * 128 + tid;
        rp[tid]       = (const char*)(mem + (size_t)g_hidx[R] * D);
        rp[128 + tid] = (const char*)(mem + (size_t)g_gidx[R] * D);
        rp[256 + tid] = br ? (const char*)(pos_emb + (size_t)g_fidx1[R] * D)
                           : (const char*)((g_pick[R] ? msg_s : msg_d) + (size_t)R * D);
        rp[384 + tid] = (const char*)(g_TEtab + (size_t)br * TMAX * D + (size_t)g_trel[R] * D);
    }
    __syncthreads();

    // loader constants: thread covers row (tid>>1), granules j = (tid&1)*4 .. +3
    int arow = tid >> 1, ahalf = tid & 1;
    int ax7  = arow & 7;
    int wih_nrow = ((nb == 3) ? 256 : nb * 128) + arow;
    int whh_nrow = ((nb < 2) ? nb * 128 : 256) + arow;
    const float* wih_row = WihB + (size_t)wih_nrow * 512;
    const float* whh_row = WhhB + (size_t)whh_nrow * 128;

    auto issue = [&](int s) {
        if (s < NSslab) {
            int st = s % 3;
            int c, koff;
            const float* wsrc;
            bool is_wih = (nb <= 2) && (s < 16);
            if (is_wih) { c = s >> 2; koff = (s & 3) * 32; wsrc = wih_row + s * 32; }
            else        { c = 0; koff = ((nb < 2) ? (s - 16) : s) * 32; wsrc = whh_row + koff; }
            const char* ap = rp[c * 128 + arow] + (size_t)koff * 4;
            uint32_t ad = su + A_OFF + st * 16384 + arow * 128;
            uint32_t wd = su + W_OFF + st * 16384 + arow * 128;
            #pragma unroll
            for (int q = 0; q < 4; ++q) {
                int j = ahalf * 4 + q;
                uint32_t sw = (uint32_t)((j ^ ax7) << 4);
                cp16(ad + sw, ap + j * 16);
                cp16(wd + sw, (const char*)wsrc + j * 16);
            }
        }
        asm volatile("cp.async.commit_group;\n");
    };

    // fragment-load lane constants
    int a_l  = lane & 15, a_kh = lane >> 4, a_x7 = a_l & 7;
    uint32_t aRow = (uint32_t)((wm * 64 + a_l) * 128);
    int b_l  = (lane & 7) + ((lane >> 4) << 3);
    int b_kh = (lane >> 3) & 1;
    int b_x7 = lane & 7;
    uint32_t bRow0 = (uint32_t)((wn * 32 + b_l) * 128);

    float acc[4][4][4];
    #pragma unroll
    for (int i = 0; i < 4; ++i)
        #pragma unroll
        for (int j = 0; j < 4; ++j)
            #pragma unroll
            for (int q = 0; q < 4; ++q) acc[i][j][q] = 0.f;

    issue(0);
    issue(1);

    for (int s = 0; s < NSslab; ++s) {
        asm volatile("cp.async.wait_group 1;\n");
        __syncthreads();
        issue(s + 2);

        uint32_t aSt = su + A_OFF + (s % 3) * 16384;
        uint32_t wSt = su + W_OFF + (s % 3) * 16384;
        #pragma unroll
        for (int k8 = 0; k8 < 4; ++k8) {
            uint32_t aj = (uint32_t)(((2 * k8 + a_kh) ^ a_x7) << 4);
            uint32_t bj = (uint32_t)(((2 * k8 + b_kh) ^ b_x7) << 4);
            uint32_t Af[4][4];
            #pragma unroll
            for (int mf = 0; mf < 4; ++mf)
                ldsm4(Af[mf], aSt + aRow + mf * 2048 + aj);
            uint32_t Bf[2][4];
            #pragma unroll
            for (int p = 0; p < 2; ++p)
                ldsm4(Bf[p], wSt + bRow0 + p * 2048 + bj);
            #pragma unroll
            for (int nf = 0; nf < 4; ++nf) {
                uint32_t b0 = Bf[nf >> 1][(nf & 1) * 2];
                uint32_t b1 = Bf[nf >> 1][(nf & 1) * 2 + 1];
                #pragma unroll
                for (int mf = 0; mf < 4; ++mf)
                    mma_tf32(&acc[mf][nf][0], Af[mf], b0, b1);
            }
        }
    }

    // store to G
    size_t gb = (size_t)br * NROWS * 512;
    #pragma unroll
    for (int mf = 0; mf < 4; ++mf) {
        int r = rb * 128 + wm * 64 + mf * 16 + (lane >> 2);
        #pragma unroll
        for (int nf = 0; nf < 4; ++nf) {
            int col = nb * 128 + wn * 32 + nf * 8 + (lane & 3) * 2;
            *(float2*)&g_G[gb + (size_t)r * 512 + col]       = make_float2(acc[mf][nf][0], acc[mf][nf][1]);
            *(float2*)&g_G[gb + (size_t)(r + 8) * 512 + col] = make_float2(acc[mf][nf][2], acc[mf][nf][3]);
        }
    }
}

// ---------------- GRU epilogue ----------------
__global__ void gru_kernel(const float* __restrict__ memory, const float* __restrict__ pos_mem,
                           const float* __restrict__ bih0, const float* __restrict__ bhh0,
                           const float* __restrict__ bih1, const float* __restrict__ bhh1,
                           float* __restrict__ out)
{
    int row = blockIdx.x;
    int j   = threadIdx.x;
    int hidx = g_hidx[row];
    #pragma unroll
    for (int br = 0; br < 2; ++br) {
        const float* G   = g_G + ((size_t)br * NROWS + row) * 512;
        const float* bih = br ? bih1 : bih0;
        const float* bhh = br ? bhh1 : bhh0;
        const float* mem = br ? pos_mem : memory;
        float r  = 1.f / (1.f + expf(-(G[j]       + bih[j]       + bhh[j])));
        float z  = 1.f / (1.f + expf(-(G[128 + j] + bih[128 + j] + bhh[128 + j])));
        float nn = tanhf(G[256 + j] + bih[256 + j] + r * (G[384 + j] + bhh[256 + j]));
        float h  = mem[(size_t)hidx * D + j];
        out[((size_t)br * NROWS + row) * D + j] = (1.f - z) * nn + z * h;
    }
}

// ---------------- launch ----------------
extern "C" void kernel_launch(void* const* d_in, const int* in_sizes, int n_in,
                              void* d_out, int out_size)
{
    const int*   n_id        = (const int*)  d_in[0];
    const float* memory      = (const float*)d_in[1];
    const float* pos_mem     = (const float*)d_in[2];
    const float* pos_emb     = (const float*)d_in[3];
    const float* raw_msg_s   = (const float*)d_in[4];
    const float* raw_msg_d   = (const float*)d_in[5];
    const int*   other_s     = (const int*)  d_in[6];
    const int*   other_d     = (const int*)  d_in[7];
    const int*   t_s         = (const int*)  d_in[8];
    const int*   t_d         = (const int*)  d_in[9];
    const int*   last_update = (const int*)  d_in[10];
    const float* w_time_mem  = (const float*)d_in[11];
    const float* b_time_mem  = (const float*)d_in[12];
    const float* w_time_pos  = (const float*)d_in[13];
    const float* b_time_pos  = (const float*)d_in[14];
    const float* Wih_mem     = (const float*)d_in[15];
    const float* Whh_mem     = (const float*)d_in[16];
    const float* bih_mem     = (const float*)d_in[17];
    const float* bhh_mem     = (const float*)d_in[18];
    const float* Wih_pos     = (const float*)d_in[19];
    const float* Whh_pos     = (const float*)d_in[20];
    const float* bih_pos     = (const float*)d_in[21];
    const float* bhh_pos     = (const float*)d_in[22];
    float* out = (float*)d_out;

    cudaFuncSetAttribute(gemm_kernel, cudaFuncAttributeMaxDynamicSharedMemorySize, SMEM_SZ);

    te_table_kernel<<<TMAX, 128>>>(w_time_mem, b_time_mem, w_time_pos, b_time_pos);
    wround_kernel<<<dim3(768, 4), 256>>>(Wih_mem, Wih_pos, Whh_mem, Whh_pos);
    prep_kernel<<<NROWS / 256, 256>>>(n_id, other_s, other_d, t_s, t_d, last_update, out);

    gemm_kernel<<<dim3(NROWS / 128, 4, 2), 256, SMEM_SZ>>>(memory, pos_mem,
                                                           raw_msg_s, raw_msg_d, pos_emb);

    gru_kernel<<<NROWS, 128>>>(memory, pos_mem, bih_mem, bhh_mem, bih_pos, bhh_pos, out);
}

// round 7
// speedup vs baseline: 1.3539x; 1.0127x over previous
#include <cuda_runtime.h>
#include <cstdint>

#define NROWS 65536
#define D 128
#define TMAX 2048

// smem: rp table 4KB | 3 stages x (A 16KB + W 16KB)
#define A_OFF    4096
#define W_OFF    (4096 + 3 * 16384)
#define SMEM_SZ  (4096 + 6 * 16384)

// ---------------- scratch ----------------
__device__ float g_G[(size_t)2 * NROWS * 512];   // per row: [r_sum | z_sum | inn | hn]
__device__ float g_TEtab[2 * TMAX * D];
__device__ float g_Wih[2][384 * 512];
__device__ float g_Whh[2][384 * 128];
__device__ int g_hidx[NROWS], g_gidx[NROWS], g_trel[NROWS], g_fidx1[NROWS], g_pick[NROWS];

// ---------------- ptx helpers ----------------
__device__ __forceinline__ void mma_tf32(float* c, const uint32_t* a, uint32_t b0, uint32_t b1) {
    asm volatile(
        "mma.sync.aligned.m16n8k8.row.col.f32.tf32.tf32.f32 "
        "{%0,%1,%2,%3}, {%4,%5,%6,%7}, {%8,%9}, {%0,%1,%2,%3};\n"
        : "+f"(c[0]), "+f"(c[1]), "+f"(c[2]), "+f"(c[3])
        : "r"(a[0]), "r"(a[1]), "r"(a[2]), "r"(a[3]), "r"(b0), "r"(b1));
}
__device__ __forceinline__ void cp16(uint32_t dst, const void* src) {
    asm volatile("cp.async.cg.shared.global [%0], [%1], 16;\n" :: "r"(dst), "l"(src));
}
__device__ __forceinline__ void ldsm4(uint32_t* r, uint32_t addr) {
    asm volatile("ldmatrix.sync.aligned.m8n8.x4.shared.b16 {%0,%1,%2,%3}, [%4];"
                 : "=r"(r[0]), "=r"(r[1]), "=r"(r[2]), "=r"(r[3]) : "r"(addr));
}

// ---------------- small kernels ----------------
__global__ void te_table_kernel(const float* __restrict__ wm, const float* __restrict__ bm,
                                const float* __restrict__ wp, const float* __restrict__ bp)
{
    int t = blockIdx.x, k = threadIdx.x;
    float tf = (float)t;
    g_TEtab[t * D + k]            = cosf(tf * wm[k] + bm[k]);
    g_TEtab[TMAX * D + t * D + k] = cosf(tf * wp[k] + bp[k]);
}

__global__ void wround_kernel(const float* __restrict__ Wih0, const float* __restrict__ Wih1,
                              const float* __restrict__ Whh0, const float* __restrict__ Whh1)
{
    int which = blockIdx.y;
    int n = (which < 2) ? 384 * 512 : 384 * 128;
    int i = blockIdx.x * 256 + threadIdx.x;
    if (i >= n) return;
    const float* s = (which == 0) ? Wih0 : (which == 1) ? Wih1 : (which == 2) ? Whh0 : Whh1;
    float* dv      = (which == 0) ? g_Wih[0] : (which == 1) ? g_Wih[1] : (which == 2) ? g_Whh[0] : g_Whh[1];
    uint32_t u; asm("cvt.rna.tf32.f32 %0, %1;" : "=r"(u) : "f"(s[i]));
    dv[i] = __uint_as_float(u);
}

__global__ void prep_kernel(const int* __restrict__ n_id,
                            const int* __restrict__ other_s, const int* __restrict__ other_d,
                            const int* __restrict__ t_s, const int* __restrict__ t_d,
                            const int* __restrict__ last_update,
                            float* __restrict__ out)
{
    int row = blockIdx.x * 256 + threadIdx.x;
    if (row >= NROWS) return;
    int ts = t_s[row], td = t_d[row];
    bool pick = (ts >= td);
    int nid = n_id[row];
    int tpick = pick ? ts : td;
    g_hidx[row]  = nid;
    g_gidx[row]  = pick ? other_s[row] : other_d[row];
    g_trel[row]  = tpick - last_update[nid];
    g_pick[row]  = pick ? 1 : 0;
    g_fidx1[row] = pick ? nid : other_d[row];
    out[(size_t)2 * NROWS * D + row] = (float)tpick;
}

// ---------------- pipelined TF32 GEMM, 512 threads, 4x4 warp grid ----------------
// grid (512 row-blocks, 4 gate-blocks, 2 branches); BM=128, BN=128, BK=32.
// gates: nb0=r_sum (20 slabs: 16 Wih + 4 Whh), nb1=z_sum (20), nb2=inn (16), nb3=hn (4)
__global__ void __launch_bounds__(512, 2)
gemm_kernel(const float* __restrict__ memory, const float* __restrict__ pos_mem,
            const float* __restrict__ msg_s,  const float* __restrict__ msg_d,
            const float* __restrict__ pos_emb)
{
    extern __shared__ char sm[];
    const char** rp = (const char**)sm;
    uint32_t su = (uint32_t)__cvta_generic_to_shared(sm);

    int br = blockIdx.z, nb = blockIdx.y, rb = blockIdx.x;
    int NSslab = (nb == 3) ? 4 : ((nb == 2) ? 16 : 20);

    const float* mem  = br ? pos_mem : memory;
    const float* WihB = g_Wih[br];
    const float* WhhB = g_Whh[br];

    int tid = threadIdx.x, lane = tid & 31, warp = tid >> 5;
    int wm = warp & 3, wn = warp >> 2;

    if (tid < 128) {
        int R = rb * 128 + tid;
        rp[tid]       = (const char*)(mem + (size_t)g_hidx[R] * D);
        rp[128 + tid] = (const char*)(mem + (size_t)g_gidx[R] * D);
        rp[256 + tid] = br ? (const char*)(pos_emb + (size_t)g_fidx1[R] * D)
                           : (const char*)((g_pick[R] ? msg_s : msg_d) + (size_t)R * D);
        rp[384 + tid] = (const char*)(g_TEtab + (size_t)br * TMAX * D + (size_t)g_trel[R] * D);
    }
    __syncthreads();

    // loader constants: thread covers row (tid>>2), granule pair j0 = (tid&3)*2
    int arow = tid >> 2;
    int j0   = (tid & 3) * 2;
    int ax7  = arow & 7;
    int wih_nrow = ((nb == 3) ? 256 : nb * 128) + arow;
    int whh_nrow = ((nb < 2) ? nb * 128 : 256) + arow;
    const float* wih_row = WihB + (size_t)wih_nrow * 512;
    const float* whh_row = WhhB + (size_t)whh_nrow * 128;

    auto issue = [&](int s) {
        if (s < NSslab) {
            int st = s % 3;
            int c, koff;
            const float* wsrc;
            bool is_wih = (nb <= 2) && (s < 16);
            if (is_wih) { c = s >> 2; koff = (s & 3) * 32; wsrc = wih_row + s * 32; }
            else        { c = 0; koff = ((nb < 2) ? (s - 16) : s) * 32; wsrc = whh_row + koff; }
            const char* ap = rp[c * 128 + arow] + (size_t)koff * 4;
            uint32_t ad = su + A_OFF + st * 16384 + arow * 128;
            uint32_t wd = su + W_OFF + st * 16384 + arow * 128;
            #pragma unroll
            for (int q = 0; q < 2; ++q) {
                int j = j0 + q;
                uint32_t sw = (uint32_t)((j ^ ax7) << 4);
                cp16(ad + sw, ap + j * 16);
                cp16(wd + sw, (const char*)wsrc + j * 16);
            }
        }
        asm volatile("cp.async.commit_group;\n");
    };

    // fragment-load lane constants
    int a_l  = lane & 15, a_kh = lane >> 4, a_x7 = a_l & 7;
    uint32_t aRow = (uint32_t)((wm * 32 + a_l) * 128);
    int b_l  = (lane & 7) + ((lane >> 4) << 3);
    int b_kh = (lane >> 3) & 1;
    int b_x7 = lane & 7;
    uint32_t bRow0 = (uint32_t)((wn * 32 + b_l) * 128);

    float acc[2][4][4];
    #pragma unroll
    for (int i = 0; i < 2; ++i)
        #pragma unroll
        for (int j = 0; j < 4; ++j)
            #pragma unroll
            for (int q = 0; q < 4; ++q) acc[i][j][q] = 0.f;

    issue(0);
    issue(1);

    for (int s = 0; s < NSslab; ++s) {
        asm volatile("cp.async.wait_group 1;\n");
        __syncthreads();
        issue(s + 2);

        uint32_t aSt = su + A_OFF + (s % 3) * 16384;
        uint32_t wSt = su + W_OFF + (s % 3) * 16384;
        #pragma unroll
        for (int k8 = 0; k8 < 4; ++k8) {
            uint32_t aj = (uint32_t)(((2 * k8 + a_kh) ^ a_x7) << 4);
            uint32_t bj = (uint32_t)(((2 * k8 + b_kh) ^ b_x7) << 4);
            uint32_t Af[2][4];
            #pragma unroll
            for (int mf = 0; mf < 2; ++mf)
                ldsm4(Af[mf], aSt + aRow + mf * 2048 + aj);
            uint32_t Bf[2][4];
            #pragma unroll
            for (int p = 0; p < 2; ++p)
                ldsm4(Bf[p], wSt + bRow0 + p * 2048 + bj);
            #pragma unroll
            for (int nf = 0; nf < 4; ++nf) {
                uint32_t b0 = Bf[nf >> 1][(nf & 1) * 2];
                uint32_t b1 = Bf[nf >> 1][(nf & 1) * 2 + 1];
                #pragma unroll
                for (int mf = 0; mf < 2; ++mf)
                    mma_tf32(&acc[mf][nf][0], Af[mf], b0, b1);
            }
        }
    }

    // store to G
    size_t gb = (size_t)br * NROWS * 512;
    #pragma unroll
    for (int mf = 0; mf < 2; ++mf) {
        int r = rb * 128 + wm * 32 + mf * 16 + (lane >> 2);
        #pragma unroll
        for (int nf = 0; nf < 4; ++nf) {
            int col = nb * 128 + wn * 32 + nf * 8 + (lane & 3) * 2;
            *(float2*)&g_G[gb + (size_t)r * 512 + col]       = make_float2(acc[mf][nf][0], acc[mf][nf][1]);
            *(float2*)&g_G[gb + (size_t)(r + 8) * 512 + col] = make_float2(acc[mf][nf][2], acc[mf][nf][3]);
        }
    }
}

// ---------------- GRU epilogue: warp per row, float4 ----------------
__global__ void gru_kernel(const float* __restrict__ memory, const float* __restrict__ pos_mem,
                           const float* __restrict__ bih0, const float* __restrict__ bhh0,
                           const float* __restrict__ bih1, const float* __restrict__ bhh1,
                           float* __restrict__ out)
{
    int warp = threadIdx.x >> 5, lane = threadIdx.x & 31;
    int row = blockIdx.x * 8 + warp;
    int br  = blockIdx.y;
    int j   = lane * 4;
    const float* G   = g_G + ((size_t)br * NROWS + row) * 512;
    const float* bih = br ? bih1 : bih0;
    const float* bhh = br ? bhh1 : bhh0;
    const float* mem = br ? pos_mem : memory;
    float4 gr = *(const float4*)&G[j];
    float4 gz = *(const float4*)&G[128 + j];
    float4 gi = *(const float4*)&G[256 + j];
    float4 gh = *(const float4*)&G[384 + j];
    float4 b1r = *(const float4*)&bih[j],       b2r = *(const float4*)&bhh[j];
    float4 b1z = *(const float4*)&bih[128 + j], b2z = *(const float4*)&bhh[128 + j];
    float4 b1n = *(const float4*)&bih[256 + j], b2n = *(const float4*)&bhh[256 + j];
    float4 hv  = *(const float4*)&mem[(size_t)g_hidx[row] * D + j];
    float o[4];
    const float* grp = &gr.x; const float* gzp = &gz.x; const float* gip = &gi.x; const float* ghp = &gh.x;
    const float* b1rp = &b1r.x; const float* b2rp = &b2r.x;
    const float* b1zp = &b1z.x; const float* b2zp = &b2z.x;
    const float* b1np = &b1n.x; const float* b2np = &b2n.x;
    const float* hp = &hv.x;
    #pragma unroll
    for (int q = 0; q < 4; ++q) {
        float r = 1.f / (1.f + expf(-(grp[q] + b1rp[q] + b2rp[q])));
        float z = 1.f / (1.f + expf(-(gzp[q] + b1zp[q] + b2zp[q])));
        float n = tanhf(gip[q] + b1np[q] + r * (ghp[q] + b2np[q]));
        o[q] = (1.f - z) * n + z * hp[q];
    }
    *(float4*)&out[((size_t)br * NROWS + row) * D + j] = make_float4(o[0], o[1], o[2], o[3]);
}

// ---------------- launch ----------------
extern "C" void kernel_launch(void* const* d_in, const int* in_sizes, int n_in,
                              void* d_out, int out_size)
{
    const int*   n_id        = (const int*)  d_in[0];
    const float* memory      = (const float*)d_in[1];
    const float* pos_mem     = (const float*)d_in[2];
    const float* pos_emb     = (const float*)d_in[3];
    const float* raw_msg_s   = (const float*)d_in[4];
    const float* raw_msg_d   = (const float*)d_in[5];
    const int*   other_s     = (const int*)  d_in[6];
    const int*   other_d     = (const int*)  d_in[7];
    const int*   t_s         = (const int*)  d_in[8];
    const int*   t_d         = (const int*)  d_in[9];
    const int*   last_update = (const int*)  d_in[10];
    const float* w_time_mem  = (const float*)d_in[11];
    const float* b_time_mem  = (const float*)d_in[12];
    const float* w_time_pos  = (const float*)d_in[13];
    const float* b_time_pos  = (const float*)d_in[14];
    const float* Wih_mem     = (const float*)d_in[15];
    const float* Whh_mem     = (const float*)d_in[16];
    const float* bih_mem     = (const float*)d_in[17];
    const float* bhh_mem     = (const float*)d_in[18];
    const float* Wih_pos     = (const float*)d_in[19];
    const float* Whh_pos     = (const float*)d_in[20];
    const float* bih_pos     = (const float*)d_in[21];
    const float* bhh_pos     = (const float*)d_in[22];
    float* out = (float*)d_out;

    cudaFuncSetAttribute(gemm_kernel, cudaFuncAttributeMaxDynamicSharedMemorySize, SMEM_SZ);

    te_table_kernel<<<TMAX, 128>>>(w_time_mem, b_time_mem, w_time_pos, b_time_pos);
    wround_kernel<<<dim3(768, 4), 256>>>(Wih_mem, Wih_pos, Whh_mem, Whh_pos);
    prep_kernel<<<NROWS / 256, 256>>>(n_id, other_s, other_d, t_s, t_d, last_update, out);

    gemm_kernel<<<dim3(NROWS / 128, 4, 2), 512, SMEM_SZ>>>(memory, pos_mem,
                                                           raw_msg_s, raw_msg_d, pos_emb);

    gru_kernel<<<dim3(NROWS / 8, 2), 256>>>(memory, pos_mem, bih_mem, bhh_mem, bih_pos, bhh_pos, out);
}

// round 8
// speedup vs baseline: 2.2224x; 1.6415x over previous
#include <cuda_runtime.h>
#include <cuda_fp16.h>
#include <cstdint>

#define NROWS 65536
#define D 128
#define TMAX 2048

// smem: rp 4KB | 3 stages x (A 16KB + W 16KB)
#define A_OFF   4096
#define STAGE   32768
#define SMEM_SZ (4096 + 3 * 32768)

// ---------------- scratch ----------------
__device__ float  g_G[(size_t)2 * NROWS * 512];   // per row: [r_sum | z_sum | inn | hn]
__device__ __half g_mem16[2][(size_t)NROWS * D];
__device__ __half g_feat16[2][(size_t)NROWS * D];
__device__ __half g_TEtab16[2 * TMAX * D];
__device__ __half g_Wih16[2][384 * 512];
__device__ __half g_Whh16[2][384 * 128];
__device__ int g_hidx[NROWS], g_gidx[NROWS], g_trel[NROWS], g_fidx1[NROWS], g_pick[NROWS];

// ---------------- ptx helpers ----------------
__device__ __forceinline__ void mma_f16(float* c, const uint32_t* a, uint32_t b0, uint32_t b1) {
    asm volatile(
        "mma.sync.aligned.m16n8k16.row.col.f32.f16.f16.f32 "
        "{%0,%1,%2,%3}, {%4,%5,%6,%7}, {%8,%9}, {%0,%1,%2,%3};\n"
        : "+f"(c[0]), "+f"(c[1]), "+f"(c[2]), "+f"(c[3])
        : "r"(a[0]), "r"(a[1]), "r"(a[2]), "r"(a[3]), "r"(b0), "r"(b1));
}
__device__ __forceinline__ void cp16(uint32_t dst, const void* src) {
    asm volatile("cp.async.cg.shared.global [%0], [%1], 16;\n" :: "r"(dst), "l"(src));
}
__device__ __forceinline__ void ldsm4(uint32_t* r, uint32_t addr) {
    asm volatile("ldmatrix.sync.aligned.m8n8.x4.shared.b16 {%0,%1,%2,%3}, [%4];"
                 : "=r"(r[0]), "=r"(r[1]), "=r"(r[2]), "=r"(r[3]) : "r"(addr));
}

// ---------------- one-time conversion kernels ----------------
__global__ void te_table16_kernel(const float* __restrict__ wm, const float* __restrict__ bm,
                                  const float* __restrict__ wp, const float* __restrict__ bp)
{
    int t = blockIdx.x, k = threadIdx.x;
    float tf = (float)t;
    g_TEtab16[t * D + k]            = __float2half_rn(cosf(tf * wm[k] + bm[k]));
    g_TEtab16[TMAX * D + t * D + k] = __float2half_rn(cosf(tf * wp[k] + bp[k]));
}

__global__ void wround16_kernel(const float* __restrict__ Wih0, const float* __restrict__ Wih1,
                                const float* __restrict__ Whh0, const float* __restrict__ Whh1)
{
    int which = blockIdx.y;
    int n = (which < 2) ? 384 * 512 : 384 * 128;
    int i = blockIdx.x * 256 + threadIdx.x;
    if (i >= n) return;
    const float* s = (which == 0) ? Wih0 : (which == 1) ? Wih1 : (which == 2) ? Whh0 : Whh1;
    __half* d      = (which == 0) ? g_Wih16[0] : (which == 1) ? g_Wih16[1]
                   : (which == 2) ? g_Whh16[0] : g_Whh16[1];
    d[i] = __float2half_rn(s[i]);
}

__global__ void conv_mem_kernel(const float* __restrict__ m0, const float* __restrict__ m1)
{
    int arr = blockIdx.y;
    const float* s = arr ? m1 : m0;
    __half* d = g_mem16[arr];
    size_t i = ((size_t)blockIdx.x * 256 + threadIdx.x) * 4;
    float4 v = *(const float4*)(s + i);
    *(__half2*)(d + i)     = __floats2half2_rn(v.x, v.y);
    *(__half2*)(d + i + 2) = __floats2half2_rn(v.z, v.w);
}

// ---------------- descriptors + last_up ----------------
__global__ void prep_kernel(const int* __restrict__ n_id,
                            const int* __restrict__ other_s, const int* __restrict__ other_d,
                            const int* __restrict__ t_s, const int* __restrict__ t_d,
                            const int* __restrict__ last_update,
                            float* __restrict__ out)
{
    int row = blockIdx.x * 256 + threadIdx.x;
    if (row >= NROWS) return;
    int ts = t_s[row], td = t_d[row];
    bool pick = (ts >= td);
    int nid = n_id[row];
    int tpick = pick ? ts : td;
    g_hidx[row]  = nid;
    g_gidx[row]  = pick ? other_s[row] : other_d[row];
    g_trel[row]  = tpick - last_update[nid];
    g_pick[row]  = pick ? 1 : 0;
    g_fidx1[row] = pick ? nid : other_d[row];
    out[(size_t)2 * NROWS * D + row] = (float)tpick;
}

// ---------------- feature pick/gather + convert ----------------
__global__ void feat_kernel(const float* __restrict__ msg_s, const float* __restrict__ msg_d,
                            const float* __restrict__ pos_emb)
{
    int warp = threadIdx.x >> 5, lane = threadIdx.x & 31;
    int row = blockIdx.x * 4 + (warp >> 1);
    int br  = warp & 1;
    const float* src = br ? pos_emb + (size_t)g_fidx1[row] * D
                          : (g_pick[row] ? msg_s : msg_d) + (size_t)row * D;
    float4 v = *(const float4*)(src + lane * 4);
    __half* d = g_feat16[br] + (size_t)row * D + lane * 4;
    *(__half2*)d       = __floats2half2_rn(v.x, v.y);
    *(__half2*)(d + 2) = __floats2half2_rn(v.z, v.w);
}

// ---------------- pipelined FP16 GEMM, 512 threads, 4x4 warp grid, BK=64 ----------------
// grid (512 row-blocks, 4 gate-blocks, 2 branches); BM=128, BN=128.
// gates: nb0=r_sum (10 slabs: 8 Wih + 2 Whh), nb1=z_sum (10), nb2=inn (8), nb3=hn (2)
__global__ void __launch_bounds__(512, 2)
gemm16_kernel()
{
    extern __shared__ char sm[];
    const __half** rp = (const __half**)sm;
    uint32_t su = (uint32_t)__cvta_generic_to_shared(sm);

    int br = blockIdx.z, nb = blockIdx.y, rb = blockIdx.x;
    int NSslab = (nb == 3) ? 2 : ((nb == 2) ? 8 : 10);
    int whh_base = (nb < 2) ? nb * 128 : 256;

    const __half* WihB = g_Wih16[br];
    const __half* WhhB = g_Whh16[br];

    int tid = threadIdx.x, lane = tid & 31, warp = tid >> 5;
    int wm = warp & 3, wn = warp >> 2;

    if (tid < 128) {
        int R = rb * 128 + tid;
        rp[tid]       = g_mem16[br] + (size_t)g_hidx[R] * D;
        rp[128 + tid] = g_mem16[br] + (size_t)g_gidx[R] * D;
        rp[256 + tid] = g_feat16[br] + (size_t)R * D;
        rp[384 + tid] = g_TEtab16 + (size_t)br * TMAX * D + (size_t)g_trel[R] * D;
    }
    __syncthreads();

    auto issue = [&](int s) {
        if (s < NSslab) {
            int st = s % 3;
            bool is_wih = (nb <= 2) && (s < 8);
            int c     = is_wih ? (s >> 1) : 0;
            int koffA = is_wih ? (s & 1) * 128 : ((nb < 2) ? (s - 8) : s) * 128;  // bytes
            uint32_t base = su + A_OFF + st * STAGE;
            #pragma unroll
            for (int p = 0; p < 2; ++p) {
                int g = tid + p * 512;
                int row = g >> 3, j = g & 7;
                int jp = ((j ^ (row & 7)) << 4);
                cp16(base + g * 16, (const char*)rp[c * 128 + row] + koffA + jp);
                const char* wsrc;
                if (is_wih) wsrc = (const char*)(WihB + (size_t)(nb * 128 + row) * 512) + s * 128 + jp;
                else        wsrc = (const char*)(WhhB + (size_t)(whh_base + row) * 128) + koffA + jp;
                cp16(base + 16384 + g * 16, wsrc);
            }
        }
        asm volatile("cp.async.commit_group;\n");
    };

    // fragment lane constants (row&7 == lane&7 for all tiles)
    int x7 = lane & 7;
    int a_kh = lane >> 4;
    int b_kh = (lane >> 3) & 1;
    uint32_t aRow = (uint32_t)((wm * 32 + ((lane >> 3) & 1) * 8 + (lane & 7)) * 128);
    uint32_t bRow = (uint32_t)((wn * 32 + (lane >> 4) * 8 + (lane & 7)) * 128);

    float acc[2][4][4];
    #pragma unroll
    for (int i = 0; i < 2; ++i)
        #pragma unroll
        for (int j = 0; j < 4; ++j)
            #pragma unroll
            for (int q = 0; q < 4; ++q) acc[i][j][q] = 0.f;

    issue(0);
    issue(1);

    for (int s = 0; s < NSslab; ++s) {
        asm volatile("cp.async.wait_group 1;\n");
        __syncthreads();
        issue(s + 2);

        uint32_t aSt = su + A_OFF + (s % 3) * STAGE;
        uint32_t wSt = aSt + 16384;
        #pragma unroll
        for (int s2 = 0; s2 < 4; ++s2) {
            uint32_t aj = (uint32_t)(((s2 * 2 + a_kh) ^ x7) << 4);
            uint32_t bj = (uint32_t)(((s2 * 2 + b_kh) ^ x7) << 4);
            uint32_t Af[2][4];
            #pragma unroll
            for (int mf = 0; mf < 2; ++mf)
                ldsm4(Af[mf], aSt + aRow + mf * 2048 + aj);
            uint32_t Bf[2][4];
            #pragma unroll
            for (int p = 0; p < 2; ++p)
                ldsm4(Bf[p], wSt + bRow + p * 2048 + bj);
            #pragma unroll
            for (int nf = 0; nf < 4; ++nf) {
                uint32_t b0 = Bf[nf >> 1][(nf & 1) * 2];
                uint32_t b1 = Bf[nf >> 1][(nf & 1) * 2 + 1];
                #pragma unroll
                for (int mf = 0; mf < 2; ++mf)
                    mma_f16(&acc[mf][nf][0], Af[mf], b0, b1);
            }
        }
    }

    // store to G
    size_t gb = (size_t)br * NROWS * 512;
    #pragma unroll
    for (int mf = 0; mf < 2; ++mf) {
        int r = rb * 128 + wm * 32 + mf * 16 + (lane >> 2);
        #pragma unroll
        for (int nf = 0; nf < 4; ++nf) {
            int col = nb * 128 + wn * 32 + nf * 8 + (lane & 3) * 2;
            *(float2*)&g_G[gb + (size_t)r * 512 + col]       = make_float2(acc[mf][nf][0], acc[mf][nf][1]);
            *(float2*)&g_G[gb + (size_t)(r + 8) * 512 + col] = make_float2(acc[mf][nf][2], acc[mf][nf][3]);
        }
    }
}

// ---------------- GRU epilogue: warp per row, float4 ----------------
__global__ void gru_kernel(const float* __restrict__ memory, const float* __restrict__ pos_mem,
                           const float* __restrict__ bih0, const float* __restrict__ bhh0,
                           const float* __restrict__ bih1, const float* __restrict__ bhh1,
                           float* __restrict__ out)
{
    int warp = threadIdx.x >> 5, lane = threadIdx.x & 31;
    int row = blockIdx.x * 8 + warp;
    int br  = blockIdx.y;
    int j   = lane * 4;
    const float* G   = g_G + ((size_t)br * NROWS + row) * 512;
    const float* bih = br ? bih1 : bih0;
    const float* bhh = br ? bhh1 : bhh0;
    const float* mem = br ? pos_mem : memory;
    float4 gr = *(const float4*)&G[j];
    float4 gz = *(const float4*)&G[128 + j];
    float4 gi = *(const float4*)&G[256 + j];
    float4 gh = *(const float4*)&G[384 + j];
    float4 b1r = *(const float4*)&bih[j],       b2r = *(const float4*)&bhh[j];
    float4 b1z = *(const float4*)&bih[128 + j], b2z = *(const float4*)&bhh[128 + j];
    float4 b1n = *(const float4*)&bih[256 + j], b2n = *(const float4*)&bhh[256 + j];
    float4 hv  = *(const float4*)&mem[(size_t)g_hidx[row] * D + j];
    const float* grp = &gr.x; const float* gzp = &gz.x; const float* gip = &gi.x; const float* ghp = &gh.x;
    const float* b1rp = &b1r.x; const float* b2rp = &b2r.x;
    const float* b1zp = &b1z.x; const float* b2zp = &b2z.x;
    const float* b1np = &b1n.x; const float* b2np = &b2n.x;
    const float* hp = &hv.x;
    float o[4];
    #pragma unroll
    for (int q = 0; q < 4; ++q) {
        float r = 1.f / (1.f + expf(-(grp[q] + b1rp[q] + b2rp[q])));
        float z = 1.f / (1.f + expf(-(gzp[q] + b1zp[q] + b2zp[q])));
        float n = tanhf(gip[q] + b1np[q] + r * (ghp[q] + b2np[q]));
        o[q] = (1.f - z) * n + z * hp[q];
    }
    *(float4*)&out[((size_t)br * NROWS + row) * D + j] = make_float4(o[0], o[1], o[2], o[3]);
}

// ---------------- launch ----------------
extern "C" void kernel_launch(void* const* d_in, const int* in_sizes, int n_in,
                              void* d_out, int out_size)
{
    const int*   n_id        = (const int*)  d_in[0];
    const float* memory      = (const float*)d_in[1];
    const float* pos_mem     = (const float*)d_in[2];
    const float* pos_emb     = (const float*)d_in[3];
    const float* raw_msg_s   = (const float*)d_in[4];
    const float* raw_msg_d   = (const float*)d_in[5];
    const int*   other_s     = (const int*)  d_in[6];
    const int*   other_d     = (const int*)  d_in[7];
    const int*   t_s         = (const int*)  d_in[8];
    const int*   t_d         = (const int*)  d_in[9];
    const int*   last_update = (const int*)  d_in[10];
    const float* w_time_mem  = (const float*)d_in[11];
    const float* b_time_mem  = (const float*)d_in[12];
    const float* w_time_pos  = (const float*)d_in[13];
    const float* b_time_pos  = (const float*)d_in[14];
    const float* Wih_mem     = (const float*)d_in[15];
    const float* Whh_mem     = (const float*)d_in[16];
    const float* bih_mem     = (const float*)d_in[17];
    const float* bhh_mem     = (const float*)d_in[18];
    const float* Wih_pos     = (const float*)d_in[19];
    const float* Whh_pos     = (const float*)d_in[20];
    const float* bih_pos     = (const float*)d_in[21];
    const float* bhh_pos     = (const float*)d_in[22];
    float* out = (float*)d_out;

    cudaFuncSetAttribute(gemm16_kernel, cudaFuncAttributeMaxDynamicSharedMemorySize, SMEM_SZ);

    te_table16_kernel<<<TMAX, 128>>>(w_time_mem, b_time_mem, w_time_pos, b_time_pos);
    wround16_kernel<<<dim3(768, 4), 256>>>(Wih_mem, Wih_pos, Whh_mem, Whh_pos);
    conv_mem_kernel<<<dim3(NROWS * D / (256 * 4), 2), 256>>>(memory, pos_mem);
    prep_kernel<<<NROWS / 256, 256>>>(n_id, other_s, other_d, t_s, t_d, last_update, out);
    feat_kernel<<<NROWS / 4, 256>>>(raw_msg_s, raw_msg_d, pos_emb);

    gemm16_kernel<<<dim3(NROWS / 128, 4, 2), 512, SMEM_SZ>>>();

    gru_kernel<<<dim3(NROWS / 8, 2), 256>>>(memory, pos_mem, bih_mem, bhh_mem, bih_pos, bhh_pos, out);
}